// round 1
// baseline (speedup 1.0000x reference)
#include <cuda_runtime.h>

#define BB 64
#define NN 4096
#define HH 64
#define TPB 256
#define CELLS_PER_BLOCK (TPB - 1)                               // 255
#define BLOCKS_X ((NN + CELLS_PER_BLOCK - 1) / CELLS_PER_BLOCK) // 17

// tanh(x) = 1 - 2/(exp(2x)+1) = 1 - 2/(2^(x*2/ln2)+1)
// ex2/rcp approx: abs error ~1e-7; saturates correctly at +-1 for large |x|.
__device__ __forceinline__ float fast_tanh(float x) {
    float e, r;
    asm("ex2.approx.f32 %0, %1;" : "=f"(e) : "f"(x * 2.885390081777927f));
    asm("rcp.approx.f32 %0, %1;" : "=f"(r) : "f"(e + 1.0f));
    return fmaf(-2.0f, r, 1.0f);
}

__device__ __forceinline__ unsigned long long pack2(float lo, float hi) {
    unsigned long long r;
    asm("mov.b64 %0, {%1, %2};" : "=l"(r) : "f"(lo), "f"(hi));
    return r;
}

__device__ __forceinline__ void unpack2(unsigned long long v, float& lo, float& hi) {
    asm("mov.b64 {%0, %1}, %2;" : "=f"(lo), "=f"(hi) : "l"(v));
}

__global__ void __launch_bounds__(TPB, 2)
step_kernel(const float* __restrict__ u, float* __restrict__ un,
            const float* __restrict__ W1, const float* __restrict__ b1,
            const float* __restrict__ W2, const float* __restrict__ b2,
            const float* __restrict__ W3, const float* __restrict__ b3,
            const float* __restrict__ dtp, const float* __restrict__ dxp)
{
    __shared__ __align__(16) float W2s[HH * HH];   // 16 KB, row-major [k][j]
    __shared__ float w1a[HH], w1b[HH], b1s[HH], w3s[HH];
    __shared__ __align__(16) float b2s[HH];
    __shared__ float fs[TPB];
    __shared__ float b3s, coeffs;

    const int t = threadIdx.x;

    // Cooperative weight load (broadcast-friendly smem residency)
    {
        const float4* W2v = (const float4*)W2;
        float4* W2d = (float4*)W2s;
        #pragma unroll
        for (int i = t; i < HH * HH / 4; i += TPB) W2d[i] = W2v[i];
        if (t < HH) {
            w1a[t] = W1[t];        // W1[0, h]
            w1b[t] = W1[HH + t];   // W1[1, h]
            b1s[t] = b1[t];
            b2s[t] = b2[t];
            w3s[t] = W3[t];
        }
        if (t == 0) { b3s = b3[0]; coeffs = dtp[0] / dxp[0]; }
    }
    __syncthreads();

    const int row = blockIdx.y;
    const float* ur = u + (size_t)row * NN;
    float* unr = un + (size_t)row * NN;
    const int i0 = blockIdx.x * CELLS_PER_BLOCK;
    const int i = i0 + t;   // interface index in [0, NN]

    if (i <= NN) {
        int il = i - 1; if (il < 0) il = 0;
        int ir = i;     if (ir > NN - 1) ir = NN - 1;
        const float uL = ur[il];
        const float uR = ur[ir];

        // acc[p] holds packed (pre2[2p], pre2[2p+1]); init with b2
        unsigned long long acc[HH / 2];
        {
            const unsigned long long* b2p = (const unsigned long long*)b2s;
            #pragma unroll
            for (int p = 0; p < HH / 2; p++) acc[p] = b2p[p];
        }

        const ulonglong2* W2p = (const ulonglong2*)W2s;  // 4 floats per entry
        #pragma unroll 4
        for (int k = 0; k < HH; k++) {
            const float pre = fmaf(uL, w1a[k], fmaf(uR, w1b[k], b1s[k]));
            const float h = fast_tanh(pre);
            const unsigned long long hp = pack2(h, h);
            const ulonglong2* rowp = W2p + k * (HH / 4);
            #pragma unroll
            for (int q = 0; q < HH / 4; q++) {
                const ulonglong2 w = rowp[q];   // LDS.128 broadcast
                asm("fma.rn.f32x2 %0, %1, %2, %0;" : "+l"(acc[2 * q])     : "l"(hp), "l"(w.x));
                asm("fma.rn.f32x2 %0, %1, %2, %0;" : "+l"(acc[2 * q + 1]) : "l"(hp), "l"(w.y));
            }
        }

        // Layer 3: f = b3 + sum_j W3[j] * tanh(pre2[j])
        float f = b3s;
        #pragma unroll
        for (int p = 0; p < HH / 2; p++) {
            float lo, hi;
            unpack2(acc[p], lo, hi);
            f = fmaf(w3s[2 * p],     fast_tanh(lo), f);
            f = fmaf(w3s[2 * p + 1], fast_tanh(hi), f);
        }
        fs[t] = f;
    }
    __syncthreads();

    const int c = i0 + t;
    if (t < CELLS_PER_BLOCK && c < NN) {
        unr[c] = ur[c] - coeffs * (fs[t + 1] - fs[t]);
    }
}

extern "C" void kernel_launch(void* const* d_in, const int* in_sizes, int n_in,
                              void* d_out, int out_size)
{
    const float* u0 = (const float*)d_in[0];
    const float* W1 = (const float*)d_in[1];
    const float* b1 = (const float*)d_in[2];
    const float* W2 = (const float*)d_in[3];
    const float* b2 = (const float*)d_in[4];
    const float* W3 = (const float*)d_in[5];
    const float* b3 = (const float*)d_in[6];
    const float* dt = (const float*)d_in[7];
    const float* dx = (const float*)d_in[8];
    float* out = (float*)d_out;

    const int state = BB * NN;                 // elements per trajectory slice
    const int nsteps = out_size / state - 1;   // 128 for this problem

    // slice 0 = u0
    cudaMemcpyAsync(out, u0, (size_t)state * sizeof(float),
                    cudaMemcpyDeviceToDevice, 0);

    dim3 grid(BLOCKS_X, BB);
    for (int s = 0; s < nsteps; s++) {
        step_kernel<<<grid, TPB>>>(out + (size_t)s * state,
                                   out + (size_t)(s + 1) * state,
                                   W1, b1, W2, b2, W3, b3, dt, dx);
    }
}